// round 5
// baseline (speedup 1.0000x reference)
#include <cuda_runtime.h>
#include <math.h>

#define BB 16
#define SS 2048
#define DD 768
#define DD4 192          // DD/4
#define KW 3
#define ROW3 (DD*KW)     // 2304
#define NCHUNK 16
#define OPC (DD/NCHUNK)  // 48 output channels per chunk

// ---- scratch (no allocations allowed) ----
__device__ float  g_part[NCHUNK][ROW3];
__device__ float  g_weff[KW][DD];     // w_eff[k][d], d contiguous for float4 loads
__device__ float  g_beff;
__device__ float4 g_r[BB*SS];         // (r0, r1, r2, -) per (b,t)
__device__ float  g_wmain[BB*SS];
__device__ float  g_wspill[BB*SS];
__device__ int    g_firepos[BB*SS];   // per batch: step index of fire j
__device__ int    g_F[BB];            // number of fires per batch

// ============================================================
// kA1: partial w_eff over o-chunks.  grid (9, 16) x 256
// conv_w layout (O, I, K): element (o,d,k) at o*ROW3 + d*3 + k
// thread t = d*3+k  -> coalesced reads across t for fixed o.
// ============================================================
__global__ void kA1(const float* __restrict__ conv_w,
                    const float* __restrict__ lin_w) {
    int t  = blockIdx.x * blockDim.x + threadIdx.x;   // 0..2303
    int o0 = blockIdx.y * OPC;
    float acc = 0.f;
#pragma unroll 8
    for (int o = o0; o < o0 + OPC; ++o)
        acc += lin_w[o] * conv_w[o * ROW3 + t];
    g_part[blockIdx.y][t] = acc;
}

// kA2: combine partials (fixed order -> deterministic) + b_eff. grid 9 x 256
__global__ void kA2(const float* __restrict__ conv_b,
                    const float* __restrict__ lin_w,
                    const float* __restrict__ lin_b) {
    int t = blockIdx.x * blockDim.x + threadIdx.x;
    float s = 0.f;
#pragma unroll
    for (int c = 0; c < NCHUNK; ++c) s += g_part[c][t];
    g_weff[t % 3][t / 3] = s;

    if (blockIdx.x == 0) {
        __shared__ float red[256];
        float s2 = 0.f;
        for (int i = threadIdx.x; i < DD; i += 256)
            s2 += lin_w[i] * conv_b[i];
        red[threadIdx.x] = s2;
        __syncthreads();
        for (int st = 128; st > 0; st >>= 1) {
            if (threadIdx.x < st) red[threadIdx.x] += red[threadIdx.x + st];
            __syncthreads();
        }
        if (threadIdx.x == 0) g_beff = red[0] + lin_b[0];
    }
}

// ============================================================
// kB: r_k[b,t] = sum_d w_eff[d,k] * x[b,t,d].  One warp per row.
// grid BB*SS/8 x 256
// ============================================================
__global__ void kB(const float* __restrict__ x) {
    int row  = blockIdx.x * 8 + (threadIdx.x >> 5);   // 0..BB*SS-1
    int lane = threadIdx.x & 31;
    const float4* xr = (const float4*)(x) + (size_t)row * DD4;
    const float4* w0 = (const float4*)g_weff[0];
    const float4* w1 = (const float4*)g_weff[1];
    const float4* w2 = (const float4*)g_weff[2];
    float a0 = 0.f, a1 = 0.f, a2 = 0.f;
#pragma unroll
    for (int i = 0; i < 6; ++i) {
        int c = lane + i * 32;
        float4 xv = xr[c];
        float4 v0 = w0[c], v1 = w1[c], v2 = w2[c];
        a0 += xv.x*v0.x + xv.y*v0.y + xv.z*v0.z + xv.w*v0.w;
        a1 += xv.x*v1.x + xv.y*v1.y + xv.z*v1.z + xv.w*v1.w;
        a2 += xv.x*v2.x + xv.y*v2.y + xv.z*v2.z + xv.w*v2.w;
    }
#pragma unroll
    for (int off = 16; off > 0; off >>= 1) {
        a0 += __shfl_down_sync(0xffffffffu, a0, off);
        a1 += __shfl_down_sync(0xffffffffu, a1, off);
        a2 += __shfl_down_sync(0xffffffffu, a2, off);
    }
    if (lane == 0) g_r[row] = make_float4(a0, a1, a2, 0.f);
}

// ============================================================
// kC: per-batch sigmoid + fp64 prefix scan + weights/fire positions.
// grid BB x 1024, 2 timesteps per thread.
// ============================================================
__global__ void kC(const int* __restrict__ lens, float* __restrict__ lens_out) {
    int b   = blockIdx.x;
    int tid = threadIdx.x;
    int len = lens[b];
    float beff = g_beff;
    const float4* r = g_r + b * SS;

    int tbase = tid * 2;
    float a[2];
#pragma unroll
    for (int e = 0; e < 2; ++e) {
        int t = tbase + e;
        float logit = beff + r[t].y;
        if (t > 0)      logit += r[t - 1].x;
        if (t < SS - 1) logit += r[t + 1].z;
        float al = 1.f / (1.f + expf(-logit));
        a[e] = (t < len) ? al : 0.f;
    }

    double pair = (double)a[0] + (double)a[1];
    double v = pair;
    int lane = tid & 31, wid = tid >> 5;
#pragma unroll
    for (int off = 1; off < 32; off <<= 1) {
        double n = __shfl_up_sync(0xffffffffu, v, off);
        if (lane >= off) v += n;
    }
    __shared__ double wt[32], wo[32];
    if (lane == 31) wt[wid] = v;
    __syncthreads();
    if (wid == 0) {
        double u = wt[lane];
#pragma unroll
        for (int off = 1; off < 32; off <<= 1) {
            double n = __shfl_up_sync(0xffffffffu, u, off);
            if (lane >= off) u += n;
        }
        wo[lane] = u - wt[lane];   // exclusive warp offset
    }
    __syncthreads();
    double incl  = v + wo[wid];
    double excl0 = incl - pair;

    double C0 = excl0 + (double)a[0];
    double C1 = C0 + (double)a[1];
    double Ce[2] = {excl0, C0};
    double Ci[2] = {C0, C1};

#pragma unroll
    for (int e = 0; e < 2; ++e) {
        int t = tbase + e;
        double fp = floor(Ce[e]);
        double fc = floor(Ci[e]);
        float af = a[e];
        float w1, w2 = 0.f;
        if (fc > fp) {                      // fire (alpha<1 => fc == fp+1)
            float aaccf = (float)(Ce[e] - fp);   // reference-style f32 aacc
            w1 = 1.0f - aaccf;
            w2 = af - w1;
            g_firepos[b * SS + (int)fp] = t;
        } else {
            w1 = af;
        }
        g_wmain[b * SS + t]  = w1;
        g_wspill[b * SS + t] = w2;
        if (t == SS - 1) {
            int F = (int)fc;                 // total fires = floor(total masked sum)
            g_F[b] = F;
            if (lens_out) lens_out[b] = (float)F;
        }
    }
}

// ============================================================
// kD: output row (b,j) = segmented weighted sum, same t-order as reference.
// grid (SS, BB) x 192 threads (one float4 column per thread).
// ============================================================
__global__ void kD(const float* __restrict__ x, float* __restrict__ out) {
    int j = blockIdx.x, b = blockIdx.y;
    int i = threadIdx.x;                  // 0..191
    float4* o4 = (float4*)out + (size_t)(b * SS + j) * DD4 + i;
    int F = g_F[b];
    if (j >= F) { *o4 = make_float4(0.f, 0.f, 0.f, 0.f); return; }

    int p1 = g_firepos[b * SS + j];
    int p0 = (j == 0) ? 0 : g_firepos[b * SS + j - 1];
    const float4* x4 = (const float4*)x + (size_t)b * SS * DD4 + i;

    float4 acc = make_float4(0.f, 0.f, 0.f, 0.f);
    int t = p0;
    if (j > 0) {                          // spill a2*h from previous fire step
        float w = g_wspill[b * SS + p0];
        float4 h = x4[(size_t)p0 * DD4];
        acc.x = w * h.x; acc.y = w * h.y; acc.z = w * h.z; acc.w = w * h.w;
        t = p0 + 1;
    }
    for (; t <= p1; ++t) {                // interior a*h ... then a1*h at fire
        float w = g_wmain[b * SS + t];
        float4 h = x4[(size_t)t * DD4];
        acc.x += w * h.x; acc.y += w * h.y; acc.z += w * h.z; acc.w += w * h.w;
    }
    *o4 = acc;
}

// ============================================================
extern "C" void kernel_launch(void* const* d_in, const int* in_sizes, int n_in,
                              void* d_out, int out_size) {
    const float* x      = (const float*)d_in[0];   // encoder_outputs (B,S,D)
    const int*   lens   = (const int*)  d_in[1];   // encoder_lens (B,)
    const float* conv_w = (const float*)d_in[2];   // (D,D,3)
    const float* conv_b = (const float*)d_in[3];   // (D,)
    const float* lin_w  = (const float*)d_in[4];   // (1,D)
    const float* lin_b  = (const float*)d_in[5];   // (1,)
    float* out = (float*)d_out;
    float* lens_out = (out_size >= BB * SS * DD + BB) ? out + (size_t)BB * SS * DD
                                                      : nullptr;

    kA1<<<dim3(ROW3 / 256, NCHUNK), 256>>>(conv_w, lin_w);
    kA2<<<ROW3 / 256, 256>>>(conv_b, lin_w, lin_b);
    kB<<<BB * SS / 8, 256>>>(x);
    kC<<<BB, 1024>>>(lens, lens_out);
    kD<<<dim3(SS, BB), 192>>>(x, out);
}